// round 11
// baseline (speedup 1.0000x reference)
#include <cuda_runtime.h>

// Sinkhorn OT loss on 64x64 pooled grids. K = exp(-C/0.1) is exact (to fp32)
// as two 3-tap separable passes, W1 = exp(-10).
// R11: warp-autonomous windows -- ZERO intra-CTA communication in the loop.
// Each warp owns 2 grid rows and redundantly computes a 10-row x 64-col window
// (4+4 vertical halo, same error bound as R10: ~1.7e-11 pre-amplification).
// Lane = columns {2l, 2l+1}: horizontal stencil = 2 shuffles/row, vertical
// stencil = pure registers (whole column strip lives in the lane). No STS, no
// LDS, no __syncthreads, no mbarrier anywhere in the 100-halfstep loop; the
// only floors left are issue (~185 instr/warp/halfstep) and MUFU (20 RCP x 8).
// 512 warps = 128 CTAs x 128 thr = 1 warp/SMSP on 128 SMs.

#define NBATCH 16
#define ITERS  50
#define EPS    1e-8f
#define W1     4.5399929762484854e-05f   // exp(-10)

__device__ float g_pooled[2][NBATCH][4096];
__device__ float g_psum[2][NBATCH][16];    // per pool-block partial sums
__device__ float g_costs[NBATCH * 8];
__device__ int   g_done;

// ---------------------------------------------------------------- pooling
__global__ __launch_bounds__(256) void pool_kernel(const float* __restrict__ pred,
                                                   const float* __restrict__ gt) {
    __shared__ float red[8];
    const int bid    = blockIdx.x;          // 0..511
    const int tensor = bid >> 8;
    const int batch  = (bid >> 4) & 15;
    const int rb     = bid & 15;            // block of 4 pooled rows
    const float* src = (tensor ? gt : pred) + (size_t)batch * 262144;

    const int pr = rb * 4 + (threadIdx.x >> 6);
    const int pc = threadIdx.x & 63;
    const float4* p = (const float4*)(src + (size_t)pr * 4096 + pc * 8);

    float s = 0.f;
#pragma unroll
    for (int y = 0; y < 8; ++y) {
        float4 v0 = p[y * 128];
        float4 v1 = p[y * 128 + 1];
        s += (v0.x + v0.y) + (v0.z + v0.w) + (v1.x + v1.y) + (v1.z + v1.w);
    }
    g_pooled[tensor][batch][pr * 64 + pc] = s;

    float v = s;
#pragma unroll
    for (int o = 16; o; o >>= 1) v += __shfl_xor_sync(0xffffffffu, v, o);
    const int w = threadIdx.x >> 5, l = threadIdx.x & 31;
    if (l == 0) red[w] = v;
    __syncthreads();
    if (threadIdx.x == 0) {
        float tot = ((red[0] + red[1]) + (red[2] + red[3]))
                  + ((red[4] + red[5]) + (red[6] + red[7]));
        g_psum[tensor][batch][rb] = tot;
    }
}

// ---------------------------------------------------------------- sinkhorn
__global__ __launch_bounds__(128, 1) void sinkhorn_kernel(float* __restrict__ out) {
    __shared__ float wcost[4];

    const int t     = threadIdx.x;
    const int w     = t >> 5, l = t & 31;
    const int bid   = blockIdx.x;
    const int batch = bid >> 3;          // 8 CTAs per batch
    const int rb    = bid & 7;           // row-block of 8 rows (4 warps x 2)
    const int own0  = rb * 8 + w * 2;    // owned rows: own0, own0+1 (window idx 4,5)
    const int win0  = own0 - 4;          // window rows win0 .. win0+9
    const int c     = 2 * l;             // lane's columns: c, c+1

    // batch-wide sums from pool partials (fixed linear order, all threads agree)
    float asum = 0.f, bsum = 0.f;
#pragma unroll
    for (int i = 0; i < 16; ++i) {
        asum += g_psum[0][batch][i];
        bsum += g_psum[1][batch][i];
    }
    const float ra  = 1.f / fmaxf(asum, 1e-8f);
    const float rbv = 1.f / fmaxf(bsum, 1e-8f);

    // whole window in registers: 10 rows x 2 cols per lane, per field
    float2 A[10], B[10], U[10], V[10];
#pragma unroll
    for (int r = 0; r < 10; ++r) {
        const int gr = win0 + r;
        if ((unsigned)gr < 64u) {
            const float2 x = *(const float2*)&g_pooled[0][batch][gr * 64 + c];
            const float2 y = *(const float2*)&g_pooled[1][batch][gr * 64 + c];
            A[r] = make_float2(x.x * ra,  x.y * ra);
            B[r] = make_float2(y.x * rbv, y.y * rbv);
            U[r] = make_float2(1.f, 1.f);
        } else {               // outside grid: zero-pad, stays zero forever
            A[r] = make_float2(0.f, 0.f);
            B[r] = make_float2(0.f, 0.f);
            U[r] = make_float2(0.f, 0.f);
        }
    }

    // o = tg / (Ve(He(in)) + eps) on the whole window; no smem, no barriers.
    auto halfstep = [&](float2 (&o)[10], const float2 (&tg)[10],
                        const float2 (&in)[10]) {
        float2 H[10];
#pragma unroll
        for (int r = 0; r < 10; ++r) {
            float lf = __shfl_up_sync(0xffffffffu, in[r].y, 1);    // col c-1
            float rt = __shfl_down_sync(0xffffffffu, in[r].x, 1);  // col c+2
            if (l == 0)  lf = 0.f;     // true grid edge
            if (l == 31) rt = 0.f;
            H[r].x = fmaf(W1, lf + in[r].y,      in[r].x);
            H[r].y = fmaf(W1, in[r].x + rt,      in[r].y);
        }
#pragma unroll
        for (int r = 0; r < 10; ++r) {
            const float upx = r      ? H[r - 1].x : 0.f;   // vertical: registers
            const float upy = r      ? H[r - 1].y : 0.f;
            const float dnx = (r < 9) ? H[r + 1].x : 0.f;
            const float dny = (r < 9) ? H[r + 1].y : 0.f;
            const float dx = fmaf(W1, upx + dnx, H[r].x + EPS);
            const float dy = fmaf(W1, upy + dny, H[r].y + EPS);
            o[r].x = __fdividef(tg[r].x, dx);
            o[r].y = __fdividef(tg[r].y, dy);
        }
    };

    for (int it = 0; it < ITERS; ++it) {
        halfstep(V, B, U);     // v = b / (K u + eps)
        halfstep(U, A, V);     // u = a / (K v + eps)
    }

    // ---- cost over owned rows (window idx 4,5):
    //      Mv = Hg(v) + W1*(T[r-1]+T[r+1]),  T = v + 2*Hg(v) ----
    float2 HG[4], T[4];        // rows 3..6
#pragma unroll
    for (int k = 0; k < 4; ++k) {
        const int r = 3 + k;
        float lf = __shfl_up_sync(0xffffffffu, V[r].y, 1);
        float rt = __shfl_down_sync(0xffffffffu, V[r].x, 1);
        if (l == 0)  lf = 0.f;
        if (l == 31) rt = 0.f;
        HG[k].x = W1 * (lf + V[r].y);
        HG[k].y = W1 * (V[r].x + rt);
        T[k].x  = fmaf(2.f, HG[k].x, V[r].x);
        T[k].y  = fmaf(2.f, HG[k].y, V[r].y);
    }
    float local = 0.f;
    {
        float mvx = fmaf(W1, T[0].x + T[2].x, HG[1].x);   // owned row own0 (k=1)
        float mvy = fmaf(W1, T[0].y + T[2].y, HG[1].y);
        local = fmaf(U[4].x, mvx, fmaf(U[4].y, mvy, local));
        mvx = fmaf(W1, T[1].x + T[3].x, HG[2].x);         // owned row own0+1 (k=2)
        mvy = fmaf(W1, T[1].y + T[3].y, HG[2].y);
        local = fmaf(U[5].x, mvx, fmaf(U[5].y, mvy, local));
    }
#pragma unroll
    for (int o = 16; o; o >>= 1) local += __shfl_xor_sync(0xffffffffu, local, o);
    if (l == 0) wcost[w] = local;
    __syncthreads();

    if (t == 0) {
        g_costs[bid] = (wcost[0] + wcost[1]) + (wcost[2] + wcost[3]);
        __threadfence();
        const int prev = atomicAdd(&g_done, 1);
        if (prev == 8 * NBATCH - 1) {
            g_done = 0;
            __threadfence();
            float s = 0.f;
#pragma unroll
            for (int bb = 0; bb < NBATCH; ++bb) {
                float as = 0.f, bs = 0.f;
#pragma unroll
                for (int i = 0; i < 16; ++i) {
                    as += g_psum[0][bb][i];
                    bs += g_psum[1][bb][i];
                }
                float cst = 0.f;
#pragma unroll
                for (int k = 0; k < 8; ++k) cst += g_costs[8 * bb + k];
                s += ((as > 0.5f) && (bs > 0.5f)) ? cst : 0.f;
            }
            out[0] = s * (1.f / (float)NBATCH);
        }
    }
}

extern "C" void kernel_launch(void* const* d_in, const int* in_sizes, int n_in,
                              void* d_out, int out_size) {
    (void)in_sizes; (void)n_in; (void)out_size;
    const float* pred = (const float*)d_in[0];
    const float* gt   = (const float*)d_in[1];
    pool_kernel<<<512, 256>>>(pred, gt);
    sinkhorn_kernel<<<NBATCH * 8, 128>>>((float*)d_out);
}